// round 2
// baseline (speedup 1.0000x reference)
#include <cuda_runtime.h>
#include <cuda_bf16.h>
#include <math.h>

// ---------------------------------------------------------------------------
// Problem: HPNETLoss
//   out[0] = sum(weight * (confidence - confidence_gt)^2) / 65536          (16.7M elems)
//   out[1] = sum(mask * (dr[:,0]-ann[:,0])^2) / N                          (N=8192)
//   out[2] = sum(mask * min(||Mgt-Mp||F, ||Mgt-Mp@RY||F)) / N
// Inputs (metadata order):
//   0: confidence     float32 (B,1,H,W)  = 16777216
//   1: confidence_gt  float32 (B,1,H,W)  = 16777216
//   2: weight         float32 (B,H,W)    = 16777216
//   3: depth_and_rotation float32 (N,5)
//   4: ann_values     float32 (N,5)
//   5: ann_flags      int32 (bool promoted by harness)
// Output: 3x float32
// ---------------------------------------------------------------------------

__global__ void zero_out_kernel(float* out, int n) {
    int i = blockIdx.x * blockDim.x + threadIdx.x;
    if (i < n) out[i] = 0.0f;
}

// Block-level reduction helper: returns block sum in thread 0.
__device__ __forceinline__ float block_reduce(float v) {
    __shared__ float warp_sums[32];
    int lane = threadIdx.x & 31;
    int wid  = threadIdx.x >> 5;
    #pragma unroll
    for (int off = 16; off > 0; off >>= 1)
        v += __shfl_down_sync(0xFFFFFFFFu, v, off);
    if (lane == 0) warp_sums[wid] = v;
    __syncthreads();
    int nwarps = (blockDim.x + 31) >> 5;
    v = (threadIdx.x < nwarps) ? warp_sums[threadIdx.x] : 0.0f;
    if (wid == 0) {
        #pragma unroll
        for (int off = 16; off > 0; off >>= 1)
            v += __shfl_down_sync(0xFFFFFFFFu, v, off);
    }
    return v;
}

__global__ void confidence_loss_kernel(const float4* __restrict__ conf,
                                       const float4* __restrict__ gt,
                                       const float4* __restrict__ wgt,
                                       float* __restrict__ out,
                                       long n4) {
    float acc = 0.0f;
    long stride = (long)gridDim.x * blockDim.x;
    for (long i = (long)blockIdx.x * blockDim.x + threadIdx.x; i < n4; i += stride) {
        float4 c = conf[i];
        float4 g = gt[i];
        float4 w = wgt[i];
        float d0 = c.x - g.x;
        float d1 = c.y - g.y;
        float d2 = c.z - g.z;
        float d3 = c.w - g.w;
        acc = fmaf(w.x * d0, d0, acc);
        acc = fmaf(w.y * d1, d1, acc);
        acc = fmaf(w.z * d2, d2, acc);
        acc = fmaf(w.w * d3, d3, acc);
    }
    float bsum = block_reduce(acc);
    if (threadIdx.x == 0)
        atomicAdd(&out[0], bsum * (1.0f / 65536.0f));
}

__device__ __forceinline__ void quat2mat(float q0, float q1, float q2, float q3,
                                         float m[9]) {
    m[0] = q0*q0 + q1*q1 - q2*q2 - q3*q3;
    m[1] = 2.0f * (q1*q2 - q0*q3);
    m[2] = 2.0f * (q1*q3 + q0*q2);
    m[3] = 2.0f * (q1*q2 + q0*q3);
    m[4] = q0*q0 - q1*q1 + q2*q2 - q3*q3;
    m[5] = 2.0f * (q2*q3 - q0*q1);
    m[6] = 2.0f * (q1*q3 - q0*q2);
    m[7] = 2.0f * (q2*q3 + q0*q1);
    m[8] = q0*q0 - q1*q1 - q2*q2 + q3*q3;
}

__global__ void ann_loss_kernel(const float* __restrict__ dr,      // (N,5)
                                const float* __restrict__ ann,     // (N,5)
                                const int* __restrict__ flags,     // int32 (bool promoted)
                                float* __restrict__ out,
                                int N) {
    int i = blockIdx.x * blockDim.x + threadIdx.x;
    float dpart = 0.0f;
    float rpart = 0.0f;
    if (i < N) {
        if (flags[i] != 0) {
            // depth term
            float dd = dr[i*5 + 0] - ann[i*5 + 0];
            dpart = dd * dd;

            // m_pred from ann quaternion (NOT normalized, per reference)
            float mp[9];
            quat2mat(ann[i*5+1], ann[i*5+2], ann[i*5+3], ann[i*5+4], mp);

            // m_gt from normalized dr quaternion
            float q0 = dr[i*5+1], q1 = dr[i*5+2], q2 = dr[i*5+3], q3 = dr[i*5+4];
            float inv = rsqrtf(q0*q0 + q1*q1 + q2*q2 + q3*q3);
            float mg[9];
            quat2mat(q0*inv, q1*inv, q2*inv, q3*inv, mg);

            // n1^2 = ||mg - mp||^2 ; n2^2 = ||mg - mp@RY||^2
            // RY = diag(-1,1,-1): columns 0 and 2 of mp negated.
            float s1 = 0.0f, s2 = 0.0f;
            #pragma unroll
            for (int r = 0; r < 3; ++r) {
                float e00 = mg[r*3+0] - mp[r*3+0];
                float e01 = mg[r*3+1] - mp[r*3+1];
                float e02 = mg[r*3+2] - mp[r*3+2];
                s1 += e00*e00 + e01*e01 + e02*e02;
                float f00 = mg[r*3+0] + mp[r*3+0];
                float f01 = mg[r*3+1] - mp[r*3+1];
                float f02 = mg[r*3+2] + mp[r*3+2];
                s2 += f00*f00 + f01*f01 + f02*f02;
            }
            rpart = sqrtf(fminf(s1, s2));
        }
    }
    float dsum = block_reduce(dpart);
    __syncthreads();   // warp_sums shared array reused
    float rsum = block_reduce(rpart);
    if (threadIdx.x == 0) {
        float invN = 1.0f / (float)N;
        atomicAdd(&out[1], dsum * invN);
        atomicAdd(&out[2], rsum * invN);
    }
}

extern "C" void kernel_launch(void* const* d_in, const int* in_sizes, int n_in,
                              void* d_out, int out_size) {
    const float* conf = (const float*)d_in[0];
    const float* gt   = (const float*)d_in[1];
    const float* wgt  = (const float*)d_in[2];
    const float* dr   = (const float*)d_in[3];
    const float* ann  = (const float*)d_in[4];
    const int*   flags = (const int*)d_in[5];
    float* out = (float*)d_out;

    long n_elems = (long)in_sizes[0];       // 16,777,216
    long n4 = n_elems / 4;
    int N = in_sizes[5];                    // 8192

    // 1) zero the output (poisoned by harness)
    zero_out_kernel<<<1, 32>>>(out, out_size);

    // 2) big streaming reduction
    int threads = 256;
    int blocks = (int)((n4 + threads - 1) / threads);
    if (blocks > 4096) blocks = 4096;
    confidence_loss_kernel<<<blocks, threads>>>(
        (const float4*)conf, (const float4*)gt, (const float4*)wgt, out, n4);

    // 3) tiny ann loss
    int ablocks = (N + 255) / 256;
    ann_loss_kernel<<<ablocks, 256>>>(dr, ann, flags, out, N);
}

// round 3
// speedup vs baseline: 1.0641x; 1.0641x over previous
#include <cuda_runtime.h>
#include <cuda_bf16.h>
#include <math.h>

// ---------------------------------------------------------------------------
// HPNETLoss — single fused persistent-style kernel.
//   out[0] = sum(weight * (confidence - confidence_gt)^2) / 65536   (16.7M elems)
//   out[1] = sum(mask * (dr[:,0]-ann[:,0])^2) / N                   (N=8192)
//   out[2] = sum(mask * min(||Mgt-Mp||F, ||Mgt-Mp@RY||F)) / N
// Inputs: 0 conf f32[16.7M], 1 gt f32[16.7M], 2 weight f32[16.7M],
//         3 depth_and_rotation f32[N,5], 4 ann_values f32[N,5],
//         5 ann_flags int32[N] (bool promoted by harness)
// Output: 3x float32.
//
// Completion protocol: blocks atomicAdd partials into g_scratch, bump the
// wrap-around counter; the elected last block atomicExch-reads (and thereby
// resets) the scratch and writes d_out. Self-resetting -> deterministic
// across CUDA-graph replays, no separate zero kernel needed.
// ---------------------------------------------------------------------------

#define GRID_BLOCKS 1184   // 148 SMs * 8
#define BLOCK_THREADS 256

__device__ float        g_scratch[3];   // zero-initialized at module load; reset each run
__device__ unsigned int g_count;        // wraps back to 0 via atomicInc

__device__ __forceinline__ float block_reduce(float v, float* warp_sums) {
    int lane = threadIdx.x & 31;
    int wid  = threadIdx.x >> 5;
    #pragma unroll
    for (int off = 16; off > 0; off >>= 1)
        v += __shfl_down_sync(0xFFFFFFFFu, v, off);
    if (lane == 0) warp_sums[wid] = v;
    __syncthreads();
    v = (threadIdx.x < (BLOCK_THREADS / 32)) ? warp_sums[threadIdx.x] : 0.0f;
    if (wid == 0) {
        #pragma unroll
        for (int off = 16; off > 0; off >>= 1)
            v += __shfl_down_sync(0xFFFFFFFFu, v, off);
    }
    __syncthreads();   // allow warp_sums reuse by subsequent reductions
    return v;
}

__device__ __forceinline__ void quat2mat(float q0, float q1, float q2, float q3,
                                         float m[9]) {
    m[0] = q0*q0 + q1*q1 - q2*q2 - q3*q3;
    m[1] = 2.0f * (q1*q2 - q0*q3);
    m[2] = 2.0f * (q1*q3 + q0*q2);
    m[3] = 2.0f * (q1*q2 + q0*q3);
    m[4] = q0*q0 - q1*q1 + q2*q2 - q3*q3;
    m[5] = 2.0f * (q2*q3 - q0*q1);
    m[6] = 2.0f * (q1*q3 - q0*q2);
    m[7] = 2.0f * (q2*q3 + q0*q1);
    m[8] = q0*q0 - q1*q1 - q2*q2 + q3*q3;
}

__global__ __launch_bounds__(BLOCK_THREADS)
void hpnet_loss_fused(const float4* __restrict__ conf,
                      const float4* __restrict__ gt,
                      const float4* __restrict__ wgt,
                      const float*  __restrict__ dr,
                      const float*  __restrict__ ann,
                      const int*    __restrict__ flags,
                      float* __restrict__ out,
                      long n4, int N) {
    __shared__ float warp_sums[BLOCK_THREADS / 32];

    const long gid    = (long)blockIdx.x * BLOCK_THREADS + threadIdx.x;
    const long stride = (long)GRID_BLOCKS * BLOCK_THREADS;

    // ---- ann loss (only first 8192 global threads; hidden under mem latency)
    float dpart = 0.0f, rpart = 0.0f;
    for (long i = gid; i < N; i += stride) {
        if (flags[i] != 0) {
            float dd = dr[i*5 + 0] - ann[i*5 + 0];
            dpart += dd * dd;

            float mp[9];
            quat2mat(ann[i*5+1], ann[i*5+2], ann[i*5+3], ann[i*5+4], mp);

            float q0 = dr[i*5+1], q1 = dr[i*5+2], q2 = dr[i*5+3], q3 = dr[i*5+4];
            float inv = rsqrtf(q0*q0 + q1*q1 + q2*q2 + q3*q3);
            float mg[9];
            quat2mat(q0*inv, q1*inv, q2*inv, q3*inv, mg);

            // RY = diag(-1,1,-1): columns 0,2 of mp negated for the second norm
            float s1 = 0.0f, s2 = 0.0f;
            #pragma unroll
            for (int r = 0; r < 3; ++r) {
                float e0 = mg[r*3+0] - mp[r*3+0];
                float e1 = mg[r*3+1] - mp[r*3+1];
                float e2 = mg[r*3+2] - mp[r*3+2];
                s1 += e0*e0 + e1*e1 + e2*e2;
                float f0 = mg[r*3+0] + mp[r*3+0];
                float f1 = mg[r*3+1] - mp[r*3+1];
                float f2 = mg[r*3+2] + mp[r*3+2];
                s2 += f0*f0 + f1*f1 + f2*f2;
            }
            rpart += sqrtf(fminf(s1, s2));
        }
    }

    // ---- confidence loss: streaming float4 reduction
    float acc = 0.0f;
    #pragma unroll 4
    for (long i = gid; i < n4; i += stride) {
        float4 c = conf[i];
        float4 g = gt[i];
        float4 w = wgt[i];
        float d0 = c.x - g.x;
        float d1 = c.y - g.y;
        float d2 = c.z - g.z;
        float d3 = c.w - g.w;
        acc = fmaf(w.x * d0, d0, acc);
        acc = fmaf(w.y * d1, d1, acc);
        acc = fmaf(w.z * d2, d2, acc);
        acc = fmaf(w.w * d3, d3, acc);
    }

    // ---- block reductions
    float csum = block_reduce(acc,   warp_sums);
    float dsum = block_reduce(dpart, warp_sums);
    float rsum = block_reduce(rpart, warp_sums);

    if (threadIdx.x == 0) {
        if (csum != 0.0f) atomicAdd(&g_scratch[0], csum);
        if (dsum != 0.0f) atomicAdd(&g_scratch[1], dsum);
        if (rsum != 0.0f) atomicAdd(&g_scratch[2], rsum);
        __threadfence();
        unsigned int ticket = atomicInc(&g_count, GRID_BLOCKS - 1);
        if (ticket == GRID_BLOCKS - 1) {
            // last block: read + reset scratch atomically, write outputs
            float s0 = atomicExch(&g_scratch[0], 0.0f);
            float s1 = atomicExch(&g_scratch[1], 0.0f);
            float s2 = atomicExch(&g_scratch[2], 0.0f);
            float invN = 1.0f / (float)N;
            out[0] = s0 * (1.0f / 65536.0f);
            out[1] = s1 * invN;
            out[2] = s2 * invN;
        }
    }
}

extern "C" void kernel_launch(void* const* d_in, const int* in_sizes, int n_in,
                              void* d_out, int out_size) {
    const float* conf = (const float*)d_in[0];
    const float* gt   = (const float*)d_in[1];
    const float* wgt  = (const float*)d_in[2];
    const float* dr   = (const float*)d_in[3];
    const float* ann  = (const float*)d_in[4];
    const int*   flags = (const int*)d_in[5];
    float* out = (float*)d_out;

    long n4 = (long)in_sizes[0] / 4;   // 4,194,304 float4s
    int  N  = in_sizes[5];             // 8192

    hpnet_loss_fused<<<GRID_BLOCKS, BLOCK_THREADS>>>(
        (const float4*)conf, (const float4*)gt, (const float4*)wgt,
        dr, ann, flags, out, n4, N);
}